// round 17
// baseline (speedup 1.0000x reference)
#include <cuda_runtime.h>
#include <cuda_fp16.h>
#include <cstdint>

#define KDIM   64
#define NPTS   32768
#define NCODES 8192
#define PTILE  128
#define CTILE  64
#define NTH    32                  // tiles per code-quarter (2048 / CTILE)
#define TPB    256                 // 8 warps x 16 rows = 128 points

// ---------------- device scratch (no allocations allowed) ----------------
__device__ __align__(16) __half g_laf[NPTS * KDIM];
__device__ __align__(16) __half g_cbf[NCODES * KDIM];
__device__ float   g_c2h[NCODES];          // 0.5*||c||^2 (fp32 exact, for rescore)
__device__ __align__(16) __half2 g_c2f2[NCODES];  // (-c2hi, -c2lo) two-term fp16 split
__device__ int4    g_t3[4 * NPTS];         // top-3 per (quarter, point)

// ---------------- helpers ----------------
__device__ __forceinline__ uint32_t smem_u32(const void* p) {
    uint32_t a;
    asm("{ .reg .u64 t; cvta.to.shared.u64 t, %1; cvt.u32.u64 %0, t; }"
        : "=r"(a) : "l"(p));
    return a;
}
#define LDSM4(r, a)                                                          \
    asm volatile("ldmatrix.sync.aligned.m8n8.x4.shared.b16 {%0,%1,%2,%3}, [%4];" \
        : "=r"((r)[0]), "=r"((r)[1]), "=r"((r)[2]), "=r"((r)[3]) : "r"(a))

#define MMAH(D, A, B0, B1)                                                   \
    asm volatile("mma.sync.aligned.m16n8k16.row.col.f32.f16.f16.f32 "        \
        "{%0,%1,%2,%3}, {%4,%5,%6,%7}, {%8,%9}, {%0,%1,%2,%3};"              \
        : "+f"((D)[0]), "+f"((D)[1]), "+f"((D)[2]), "+f"((D)[3])             \
        : "r"((A)[0]), "r"((A)[1]), "r"((A)[2]), "r"((A)[3]),                \
          "r"(B0), "r"(B1))

#define MMAH_Z(D, A, B0, B1)                                                 \
    asm volatile("mma.sync.aligned.m16n8k16.row.col.f32.f16.f16.f32 "        \
        "{%0,%1,%2,%3}, {%4,%5,%6,%7}, {%8,%9}, {%10,%10,%10,%10};"          \
        : "=f"((D)[0]), "=f"((D)[1]), "=f"((D)[2]), "=f"((D)[3])             \
        : "r"((A)[0]), "r"((A)[1]), "r"((A)[2]), "r"((A)[3]),                \
          "r"(B0), "r"(B1), "f"(0.0f))

#define CP16(dst, src)                                                       \
    asm volatile("cp.async.cg.shared.global [%0], [%1], 16;"                 \
                 :: "r"(dst), "l"(src))
#define CP_COMMIT() asm volatile("cp.async.commit_group;" ::: "memory")
#define CP_WAIT0()  asm volatile("cp.async.wait_group 0;" ::: "memory")

// insert s into a 3-deep max list (strict >, preserves first-occurrence ties)
#define TOP3(V1, I1, V2, I2, V3, I3, s, idx) do {                            \
    if ((s) > (V3)) {                                                        \
        if ((s) > (V1)) { V3 = V2; I3 = I2; V2 = V1; I2 = I1;                \
                          V1 = (s); I1 = (idx); }                            \
        else if ((s) > (V2)) { V3 = V2; I3 = I2; V2 = (s); I2 = (idx); }     \
        else { V3 = (s); I3 = (idx); }                                       \
    }                                                                        \
} while (0)

// ---------------- prekernels ----------------
__global__ void tohalf_all(const float* __restrict__ lat,
                           const float* __restrict__ cb) {
    int i = blockIdx.x * blockDim.x + threadIdx.x;
    if (i < NPTS * KDIM) g_laf[i] = __float2half(lat[i]);
    else g_cbf[i - NPTS * KDIM] = __float2half(cb[i - NPTS * KDIM]);
}
__global__ void c2k(const float* __restrict__ cb) {
    int i = blockIdx.x * blockDim.x + threadIdx.x;
    const float* row = cb + (size_t)i * KDIM;
    float s = 0.f;
#pragma unroll
    for (int j = 0; j < KDIM; j++) s = fmaf(row[j], row[j], s);
    float c2 = 0.5f * s;
    g_c2h[i] = c2;
    __half hi = __float2half(-c2);                    // two-term split of -c2
    float  lo = (-c2) - __half2float(hi);
    g_c2f2[i] = __halves2half2(hi, __float2half(lo));
}

// ---------------- B-tile + c2 staging via cp.async (double-buffered) --------
__device__ __forceinline__ void stage_B_async(uint32_t sbB, uint32_t sbC,
                                              int tid, int gt, int b) {
    const char* src = reinterpret_cast<const char*>(g_cbf) + (size_t)gt * 8192;
    {                                              // 512 chunks / 256 threads
        int id = tid;
        int r = id >> 3, c = id & 7;
        CP16(sbB + b * 8192 + r * 128 + ((c ^ (r & 7)) * 16), src + id * 16);
        id = tid + TPB;
        r = id >> 3; c = id & 7;
        CP16(sbB + b * 8192 + r * 128 + ((c ^ (r & 7)) * 16), src + id * 16);
    }
    if (tid < 16)                                  // 64 codes x 4 B = 256 B
        CP16(sbC + b * 256 + tid * 16,
             reinterpret_cast<const char*>(g_c2f2) + (size_t)gt * 256 + tid * 16);
    CP_COMMIT();
}

// ---------------- main HMMA kernel: 1024 CTAs (point-block x code-quarter) --
__global__ __launch_bounds__(TPB, 3)
void vq_mma() {
    __shared__ __align__(16) uint4 sBq[1024];      // 16 KB: A staging, then B x2
    __shared__ __align__(16) uint32_t sc2[2][64];  // c2 fragments (half2/code)
    char* sB = reinterpret_cast<char*>(sBq);
    const uint32_t sb  = smem_u32(sBq);
    const uint32_t sbc = smem_u32(sc2);

    const int tid = threadIdx.x, lane = tid & 31, w = tid >> 5;
    const int pb      = blockIdx.x >> 2;           // point block 0..255
    const int quarter = blockIdx.x & 3;            // code quarter 0..3
    const int pbase = pb * PTILE;
    const int tbase = quarter * NTH;               // first global tile

    // ---- stage A swizzled: [128 rows][128 B] (fp16, 64 dims = 128 B/row) ----
    {
        const uint4* src = reinterpret_cast<const uint4*>(g_laf) + (size_t)pbase * 8;
#pragma unroll
        for (int i = 0; i < 4; i++) {              // 1024 chunks / 256 threads
            int id = tid + i * TPB;
            int r = id >> 3, c = id & 7;
            *reinterpret_cast<uint4*>(sB + r * 128 + ((c ^ (r & 7)) * 16)) = src[id];
        }
    }
    __syncthreads();

    // ---- A fragments into registers (held for all 32 tiles) ----
    uint32_t A[4][4];
    {
        int r = w * 16 + (lane & 15);
        int ch = lane >> 4;                        // 0/1 : low/high 16B of kchunk
#pragma unroll
        for (int kc = 0; kc < 4; kc++) {
            int c = kc * 2 + ch;
            LDSM4(A[kc], sb + r * 128 + ((c ^ (r & 7)) * 16));
        }
    }
    __syncthreads();                               // A smem now reusable for B

    // constant A fragment for the c2 K-chunk: rows of [1, 1, 0, ..., 0]
    const uint32_t one2 = ((lane & 3) == 0) ? 0x3C003C00u : 0u;  // half2(1,1)
    const uint32_t Acf[4] = {one2, one2, 0u, 0u};

    // top-3 state for two row groups (rows r, r+8 of this warp's 16)
    float v1a = -3.0e38f, v2a = -3.0e38f, v3a = -3.0e38f;
    float v1b = -3.0e38f, v2b = -3.0e38f, v3b = -3.0e38f;
    int   i1a = 0, i2a = 1, i3a = 2, i1b = 0, i2b = 1, i3b = 2;

    // n-invariant pieces of the B ldmatrix addresses
    const int rlow = lane & 7;
    const int chq  = (lane >> 3) & 3;
    const uint32_t bo0 = rlow * 128 + (((chq)     ^ rlow) * 16);
    const uint32_t bo1 = rlow * 128 + (((4 + chq) ^ rlow) * 16);
    const uint32_t co  = (lane >> 2) * 4;          // c2 fragment LDS offset

    stage_B_async(sb, sbc, tid, tbase, 0);
    CP_WAIT0();
    __syncthreads();

    for (int t = 0; t < NTH; t++) {
        const int b = t & 1;
        if (t + 1 < NTH) stage_B_async(sb, sbc, tid, tbase + t + 1, b ^ 1);
        const uint32_t bbase = sb + b * 8192;
        const uint32_t cbase = sbc + b * 256;

#pragma unroll
        for (int n = 0; n < 8; n++) {
            // c2 B-fragment: k=0,1 hold (-c2hi, -c2lo) for code n*8 + lane>>2
            uint32_t cv;
            asm volatile("ld.shared.b32 %0, [%1];" : "=r"(cv)
                         : "r"(cbase + n * 32 + co));
            uint32_t bc = ((lane & 3) == 0) ? cv : 0u;

            uint32_t B[4][2];
            {
                uint32_t tmp[4];
                LDSM4(tmp, bbase + bo0 + n * 1024);
                B[0][0] = tmp[0]; B[0][1] = tmp[1];
                B[1][0] = tmp[2]; B[1][1] = tmp[3];
                LDSM4(tmp, bbase + bo1 + n * 1024);
                B[2][0] = tmp[0]; B[2][1] = tmp[1];
                B[3][0] = tmp[2]; B[3][1] = tmp[3];
            }
            float D[4];
            MMAH_Z(D, Acf, bc, 0u);                // D = -c2 broadcast to rows
#pragma unroll
            for (int kc = 0; kc < 4; kc++) MMAH(D, A[kc], B[kc][0], B[kc][1]);

            // ---- filtered top-3: D is already the score ----
            float m = fmaxf(fmaxf(D[0], D[1]), fmaxf(D[2], D[3]));
            if (__any_sync(~0u, m > fminf(v3a, v3b))) {   // rare after warm-up
                int g0 = (tbase + t) * CTILE + n * 8 + 2 * (lane & 3);
                TOP3(v1a, i1a, v2a, i2a, v3a, i3a, D[0], g0);
                TOP3(v1a, i1a, v2a, i2a, v3a, i3a, D[1], g0 + 1);
                TOP3(v1b, i1b, v2b, i2b, v3b, i3b, D[2], g0);
                TOP3(v1b, i1b, v2b, i2b, v3b, i3b, D[3], g0 + 1);
            }
        }
        if (t + 1 < NTH) CP_WAIT0();
        __syncthreads();
    }

    // ---- merge top-3 across the 4 lanes sharing each row (disjoint codes) ---
#pragma unroll
    for (int off = 1; off <= 2; off <<= 1) {
        float w1 = __shfl_xor_sync(~0u, v1a, off), w2 = __shfl_xor_sync(~0u, v2a, off),
              w3 = __shfl_xor_sync(~0u, v3a, off);
        int   j1 = __shfl_xor_sync(~0u, i1a, off), j2 = __shfl_xor_sync(~0u, i2a, off),
              j3 = __shfl_xor_sync(~0u, i3a, off);
        TOP3(v1a, i1a, v2a, i2a, v3a, i3a, w1, j1);
        TOP3(v1a, i1a, v2a, i2a, v3a, i3a, w2, j2);
        TOP3(v1a, i1a, v2a, i2a, v3a, i3a, w3, j3);
        w1 = __shfl_xor_sync(~0u, v1b, off); w2 = __shfl_xor_sync(~0u, v2b, off);
        w3 = __shfl_xor_sync(~0u, v3b, off);
        j1 = __shfl_xor_sync(~0u, i1b, off); j2 = __shfl_xor_sync(~0u, i2b, off);
        j3 = __shfl_xor_sync(~0u, i3b, off);
        TOP3(v1b, i1b, v2b, i2b, v3b, i3b, w1, j1);
        TOP3(v1b, i1b, v2b, i2b, v3b, i3b, w2, j2);
        TOP3(v1b, i1b, v2b, i2b, v3b, i3b, w3, j3);
    }
    if ((lane & 3) == 0) {
        int r0 = lane >> 2;
        int4* dst = g_t3 + quarter * NPTS + pbase + w * 16;
        dst[r0]     = make_int4(i1a, i2a, i3a, 0);
        dst[r0 + 8] = make_int4(i1b, i2b, i3b, 0);
    }
}

// ---------------- exact fp32 rescore of the twelve candidates ----------------
__global__ void rescore_kernel(const float* __restrict__ lat,
                               const float* __restrict__ cb,
                               float* __restrict__ out) {
    int p = blockIdx.x * blockDim.x + threadIdx.x;
    int id[12];
#pragma unroll
    for (int q = 0; q < 4; q++) {
        int4 c = g_t3[q * NPTS + p];
        id[3 * q] = c.x; id[3 * q + 1] = c.y; id[3 * q + 2] = c.z;
    }
    const float4* x = reinterpret_cast<const float4*>(lat + (size_t)p * KDIM);
    float4 xr[KDIM / 4];
#pragma unroll
    for (int q = 0; q < KDIM / 4; q++) xr[q] = x[q];

    float bv = -3.0e38f; int bi = 0x7fffffff;
#pragma unroll
    for (int j = 0; j < 12; j++) {
        const float4* c = reinterpret_cast<const float4*>(cb + (size_t)id[j] * KDIM);
        float a0 = 0.f, a1 = 0.f, a2 = 0.f, a3 = 0.f;
#pragma unroll
        for (int q = 0; q < KDIM / 4; q++) {
            float4 cv = c[q];
            a0 = fmaf(xr[q].x, cv.x, a0);
            a1 = fmaf(xr[q].y, cv.y, a1);
            a2 = fmaf(xr[q].z, cv.z, a2);
            a3 = fmaf(xr[q].w, cv.w, a3);
        }
        float s = ((a0 + a1) + (a2 + a3)) - g_c2h[id[j]];
        if (s > bv || (s == bv && id[j] < bi)) { bv = s; bi = id[j]; }
    }
    out[p] = (float)bi;
}

// ---------------- launch ----------------
extern "C" void kernel_launch(void* const* d_in, const int* in_sizes, int n_in,
                              void* d_out, int out_size) {
    const float* lat = (const float*)d_in[0];
    const float* cb  = (n_in > 1) ? (const float*)d_in[1] : (const float*)d_in[0];
    int cb_idx = -1, lat_idx = -1;
    for (int i = 0; i < n_in; i++) {
        if (in_sizes[i] == 524288)  cb_idx  = i;
        if (in_sizes[i] == 8388608) lat_idx = i;
    }
    if (cb_idx >= 0) {
        cb = (const float*)d_in[cb_idx];
        for (int i = 0; i < n_in; i++)
            if (i != cb_idx && (in_sizes[i] == 2097152 || in_sizes[i] == 8388608)) {
                lat = (const float*)d_in[i]; break;
            }
    } else if (lat_idx >= 0) {
        lat = (const float*)d_in[lat_idx];
        for (int i = 0; i < n_in; i++)
            if (i != lat_idx && in_sizes[i] == 2097152) { cb = (const float*)d_in[i]; break; }
    }
    float* out = (float*)d_out;

    tohalf_all<<<((NPTS + NCODES) * KDIM) / 256, 256>>>(lat, cb);
    c2k<<<NCODES / 256, 256>>>(cb);
    vq_mma<<<(NPTS / PTILE) * 4, TPB>>>();
    rescore_kernel<<<NPTS / 128, 128>>>(lat, cb, out);
}